// round 11
// baseline (speedup 1.0000x reference)
#include <cuda_runtime.h>

#define IMG 512
#define TW 64
#define TH 32
#define KS 11
#define HALO 5
#define COLS 76              /* even-aligned halo: ow0-6 .. ow0+69 */
#define NPC 38               /* column pairs */
#define S2 77                /* float2 row stride (154 words: phase-conflict-free) */
#define RG 4                 /* output rows per vertical task */
#define NROWS (RG + KS - 1)  /* 14 input rows per task */
#define NTASK (NPC*(TH/RG))  /* 304 */
#define NTHREADS 256
/* smem: s_v1 32*77*8 + s_vq 32*77*8 = 39424 B -> 4 CTAs/SM */
#define SMEM_BYTES (TH*S2*8*2)

typedef unsigned long long u64;

__device__ double g_accum;
__device__ float g_wv[2][KS];
__device__ float g_wh[2][KS];

__device__ __forceinline__ u64 pack2(float x, float y) {
    u64 r; asm("mov.b64 %0, {%1,%2};" : "=l"(r) : "f"(x), "f"(y)); return r;
}
__device__ __forceinline__ void unpack2(u64 v, float& x, float& y) {
    asm("mov.b64 {%0,%1}, %2;" : "=f"(x), "=f"(y) : "l"(v));
}
__device__ __forceinline__ u64 fma2(u64 a, u64 b, u64 c) {
    u64 d; asm("fma.rn.f32x2 %0, %1, %2, %3;" : "=l"(d) : "l"(a), "l"(b), "l"(c)); return d;
}
__device__ __forceinline__ u64 mul2(u64 a, u64 b) {
    u64 d; asm("mul.rn.f32x2 %0, %1, %2;" : "=l"(d) : "l"(a), "l"(b)); return d;
}

/* Gaussian symmetry w[k] == w[10-k] (bit-exact: k2 = g outer g) */
#define WIDX(k) ((k) < 6 ? (k) : 10 - (k))

// Rank-1 factor reconstruction; also resets accumulator each replay.
__global__ void prep_kernel(const float* __restrict__ kern) {
    int tid = threadIdx.x;
    if (tid == 0) g_accum = 0.0;
    if (tid < 64) {
        int ch = tid >> 5, lane = tid & 31;
        const float* kc = kern + ch * KS * KS;
        float s = 0.f;
        if (lane < KS) {
            #pragma unroll
            for (int j = 0; j < KS; j++) s += kc[lane * KS + j];       // row sums
        } else if (lane < 2 * KS) {
            #pragma unroll
            for (int j = 0; j < KS; j++) s += kc[j * KS + lane - KS];  // col sums
        }
        float contrib = (lane < KS) ? s : 0.f;
        #pragma unroll
        for (int o = 16; o > 0; o >>= 1) contrib += __shfl_xor_sync(0xffffffffu, contrib, o);
        if (lane < KS)           g_wv[ch][lane] = s;
        else if (lane < 2 * KS)  g_wh[ch][lane - KS] = s / contrib;
    }
}

extern __shared__ float2 smem_dyn[];

/* accumulate one row of a column pair: xv=(x_c0,x_c1), yv=(y_c0,y_c1) */
__device__ __forceinline__ void vaccum(u64 xv, u64 yv, int tt,
                                       const u64* __restrict__ wv2,
                                       u64* ax, u64* ay, u64* aq, u64* axy) {
    u64 qv  = fma2(yv, yv, mul2(xv, xv));   // x^2+y^2 per column
    u64 xyv = mul2(xv, yv);                 // x*y per column
    #pragma unroll
    for (int i = 0; i < RG; i++) {
        int k = tt - i;
        if (k >= 0 && k < KS) {
            int wi = WIDX(k);
            ax[i]  = fma2(wv2[wi], xv,  ax[i]);
            ay[i]  = fma2(wv2[wi], yv,  ay[i]);
            aq[i]  = fma2(wv2[wi], qv,  aq[i]);
            axy[i] = fma2(wv2[wi], xyv, axy[i]);
        }
    }
}

__global__ __launch_bounds__(NTHREADS, 4)
void ssim_main(const float* __restrict__ x, const float* __restrict__ y) {
    float2* s_v1 = smem_dyn;                  // [TH][S2] (sum_x, sum_y) per col
    float2* s_vq = s_v1 + TH * S2;            // [TH][S2] (sum_q, sum_xy) per col

    const int tid = threadIdx.x;
    const int plane = blockIdx.z;             // 64 = 32 batch * 2 chan (NCHW)
    const int ch = plane & 1;
    const int oh0 = blockIdx.y * TH;
    const int ow0 = blockIdx.x * TW;
    const float* xp = x + (size_t)plane * IMG * IMG;
    const float* yp = y + (size_t)plane * IMG * IMG;

    u64 wv2[6];
    #pragma unroll
    for (int k = 0; k < 6; k++) { float w = __ldg(&g_wv[ch][k]); wv2[k] = pack2(w, w); }

    // block-uniform interior test (widened halo still inside image)
    const bool interior = (blockIdx.x >= 1) & (blockIdx.x <= 6) &
                          (blockIdx.y >= 1) & (blockIdx.y <= 14);

    // ---- stage 1: vertical conv on column pairs (LDG.64, even-aligned) ----
    for (int t = tid; t < NTASK; t += NTHREADS) {
        int m   = t % NPC;                    // column pair index
        int rgi = t / NPC;
        int rg  = rgi * RG;
        int r0  = oh0 + rg - HALO;
        int gc0 = ow0 + 2 * m - 6;            // even global column
        int sc  = 2 * m;                      // smem col of pair lane 0

        u64 ax[RG], ay[RG], aq[RG], axy[RG];
        #pragma unroll
        for (int i = 0; i < RG; i++) { ax[i] = 0ull; ay[i] = 0ull; aq[i] = 0ull; axy[i] = 0ull; }

        if (interior) {
            const u64* xb = reinterpret_cast<const u64*>(xp + (ptrdiff_t)r0 * IMG + gc0);
            const u64* yb = reinterpret_cast<const u64*>(yp + (ptrdiff_t)r0 * IMG + gc0);
            #pragma unroll
            for (int tt = 0; tt < NROWS; tt++)   // 14 rows, unpredicated LDG.64
                vaccum(__ldg(xb + tt * (IMG / 2)), __ldg(yb + tt * (IMG / 2)),
                       tt, wv2, ax, ay, aq, axy);
        } else {
            bool ok0 = (unsigned)gc0 < (unsigned)IMG;
            bool ok1 = (unsigned)(gc0 + 1) < (unsigned)IMG;
            const float* xb = xp + (ptrdiff_t)r0 * IMG + gc0;
            const float* yb = yp + (ptrdiff_t)r0 * IMG + gc0;
            #pragma unroll
            for (int tt = 0; tt < NROWS; tt++) {
                int gr = r0 + tt;
                bool rok = (unsigned)gr < (unsigned)IMG;
                float x0 = 0.f, x1 = 0.f, y0 = 0.f, y1 = 0.f;
                if (rok & ok0) { x0 = __ldg(xb + tt * IMG);     y0 = __ldg(yb + tt * IMG); }
                if (rok & ok1) { x1 = __ldg(xb + tt * IMG + 1); y1 = __ldg(yb + tt * IMG + 1); }
                vaccum(pack2(x0, x1), pack2(y0, y1), tt, wv2, ax, ay, aq, axy);
            }
        }

        // transpose-pack into per-column planes
        #pragma unroll
        for (int i = 0; i < RG; i++) {
            float x0, x1, y0, y1, q0, q1, p0, p1;
            unpack2(ax[i], x0, x1);  unpack2(ay[i], y0, y1);
            unpack2(aq[i], q0, q1);  unpack2(axy[i], p0, p1);
            int ro = (rg + i) * S2;
            *reinterpret_cast<u64*>(&s_v1[ro + sc])     = pack2(x0, y0);
            *reinterpret_cast<u64*>(&s_v1[ro + sc + 1]) = pack2(x1, y1);
            *reinterpret_cast<u64*>(&s_vq[ro + sc])     = pack2(q0, p0);
            *reinterpret_cast<u64*>(&s_vq[ro + sc + 1]) = pack2(q1, p1);
        }
    }

    __syncthreads();

    // ---- stage 2: horizontal conv, single 8-px pass per thread ----
    u64 wh2[6];
    #pragma unroll
    for (int k = 0; k < 6; k++) { float w = __ldg(&g_wh[ch][k]); wh2[k] = pack2(w, w); }

    const int row = tid & 31;      // lanes span rows -> conflict-free
    const int c0 = (tid >> 5) * 8;
    const float C1 = 1e-4f, C2 = 9e-4f;
    float lsum = 0.f;

    u64 h1[8], hq[8];
    #pragma unroll
    for (int p = 0; p < 8; p++) { h1[p] = 0ull; hq[p] = 0ull; }

    #pragma unroll
    for (int j = 0; j < 8 + KS - 1; j++) {      // 18 cols; px p needs smem cols p+1..p+11
        u64 b1 = *reinterpret_cast<const u64*>(&s_v1[row * S2 + c0 + 1 + j]);
        u64 bq = *reinterpret_cast<const u64*>(&s_vq[row * S2 + c0 + 1 + j]);
        #pragma unroll
        for (int p = 0; p < 8; p++) {
            int k = j - p;
            if (k >= 0 && k < KS) {
                int wi = WIDX(k);
                h1[p] = fma2(wh2[wi], b1, h1[p]);
                hq[p] = fma2(wh2[wi], bq, hq[p]);
            }
        }
    }

    // ---- epilogue: SSIM per pixel ----
    #pragma unroll
    for (int p = 0; p < 8; p++) {
        float mux, muy; unpack2(h1[p], mux, muy);
        float es, exy;  unpack2(hq[p], es, exy);     // es = E[x^2+y^2]
        float muxy = mux * muy;
        float sxy  = fmaf(-mux, muy, exy);
        float na   = fmaf(muxy, 2.0f, C1);
        float nb   = fmaf(sxy,  2.0f, C2);
        float m2   = fmaf(mux, mux, muy * muy);
        float dena = m2 + C1;
        float denb = (es - m2) + C2;
        lsum += __fdividef(na * nb, dena * denb);
    }

    // ---- reduction: warp -> block -> one double atomic ----
    #pragma unroll
    for (int o = 16; o > 0; o >>= 1) lsum += __shfl_xor_sync(0xffffffffu, lsum, o);
    __shared__ float wsum[NTHREADS / 32];
    if ((tid & 31) == 0) wsum[tid >> 5] = lsum;
    __syncthreads();
    if (tid == 0) {
        float b = 0.f;
        #pragma unroll
        for (int w = 0; w < NTHREADS / 32; w++) b += wsum[w];
        atomicAdd(&g_accum, (double)b);
    }
}

__global__ void finalize_kernel(float* __restrict__ out) {
    if (threadIdx.x == 0) {
        out[0] = 1.0f - (float)(g_accum * (1.0 / (32.0 * 2.0 * 512.0 * 512.0)));
    }
}

extern "C" void kernel_launch(void* const* d_in, const int* in_sizes, int n_in,
                              void* d_out, int out_size) {
    const float* x = (const float*)d_in[0];
    const float* y = (const float*)d_in[1];
    const float* kern = (const float*)d_in[2];
    float* out = (float*)d_out;

    prep_kernel<<<1, 64>>>(kern);
    dim3 grid(IMG / TW, IMG / TH, 64);
    ssim_main<<<grid, NTHREADS, SMEM_BYTES>>>(x, y);
    finalize_kernel<<<1, 32>>>(out);
}

// round 12
// speedup vs baseline: 1.1397x; 1.1397x over previous
#include <cuda_runtime.h>

#define IMG 512
#define TW 64
#define TH 32
#define KS 11
#define HALO 5
#define COLS 74              /* TW + 2*HALO */
#define S2 75                /* float2 row stride (odd -> conflict-free) */
#define RG 8                 /* output rows per vertical task */
#define NROWS (RG + KS - 1)  /* 18 input rows per task */
#define NTASK (COLS*(TH/RG)) /* 296 */
#define NTHREADS 256
/* smem: s_v1 32*75*8 + s_vq 32*75*8 = 38400 B -> 4 CTAs/SM */
#define SMEM_BYTES (TH*S2*8*2)

typedef unsigned long long u64;

__device__ double g_accum;
__device__ float g_wv[2][KS];
__device__ float g_wh[2][KS];

__device__ __forceinline__ u64 pack2(float x, float y) {
    u64 r; asm("mov.b64 %0, {%1,%2};" : "=l"(r) : "f"(x), "f"(y)); return r;
}
__device__ __forceinline__ void unpack2(u64 v, float& x, float& y) {
    asm("mov.b64 {%0,%1}, %2;" : "=f"(x), "=f"(y) : "l"(v));
}
__device__ __forceinline__ u64 fma2(u64 a, u64 b, u64 c) {
    u64 d; asm("fma.rn.f32x2 %0, %1, %2, %3;" : "=l"(d) : "l"(a), "l"(b), "l"(c)); return d;
}

/* Gaussian symmetry w[k] == w[10-k] (bit-exact: k2 = g outer g) */
#define WIDX(k) ((k) < 6 ? (k) : 10 - (k))

// Rank-1 factor reconstruction; resets accumulator each replay.
// Triggers programmatic completion as soon as results are globally visible.
__global__ void prep_kernel(const float* __restrict__ kern) {
    int tid = threadIdx.x;
    if (tid == 0) g_accum = 0.0;
    if (tid < 64) {
        int ch = tid >> 5, lane = tid & 31;
        const float* kc = kern + ch * KS * KS;
        float s = 0.f;
        if (lane < KS) {
            #pragma unroll
            for (int j = 0; j < KS; j++) s += kc[lane * KS + j];       // row sums
        } else if (lane < 2 * KS) {
            #pragma unroll
            for (int j = 0; j < KS; j++) s += kc[j * KS + lane - KS];  // col sums
        }
        float contrib = (lane < KS) ? s : 0.f;
        #pragma unroll
        for (int o = 16; o > 0; o >>= 1) contrib += __shfl_xor_sync(0xffffffffu, contrib, o);
        if (lane < KS)           g_wv[ch][lane] = s;
        else if (lane < 2 * KS)  g_wh[ch][lane - KS] = s / contrib;
    }
    __syncthreads();
    cudaTriggerProgrammaticLaunchCompletion();
}

extern __shared__ float2 smem_dyn[];

/* accumulate one input px (vx,vy) into RG row accumulators:
   stream u = (x, y), stream q = (x^2 + y^2, x*y) */
__device__ __forceinline__ void vaccum(float vx, float vy, int tt,
                                       const u64* __restrict__ wv2,
                                       u64* a1, u64* aq) {
    u64 u = pack2(vx, vy);
    float s2  = fmaf(vy, vy, vx * vx);
    float pxy = vx * vy;
    u64 q = pack2(s2, pxy);
    #pragma unroll
    for (int i = 0; i < RG; i++) {
        int k = tt - i;
        if (k >= 0 && k < KS) {
            int wi = WIDX(k);
            a1[i] = fma2(wv2[wi], u, a1[i]);
            aq[i] = fma2(wv2[wi], q, aq[i]);
        }
    }
}

__global__ __launch_bounds__(NTHREADS, 4)
void ssim_main(const float* __restrict__ x, const float* __restrict__ y) {
    float2* s_v1 = smem_dyn;                  // [TH][S2] (sum_x, sum_y)
    float2* s_vq = s_v1 + TH * S2;            // [TH][S2] (sum_{x^2+y^2}, sum_xy)

    // wait for prep's weights/accumulator reset (PDL contract)
    cudaGridDependencySynchronize();

    const int tid = threadIdx.x;
    const int plane = blockIdx.z;             // 64 = 32 batch * 2 chan (NCHW)
    const int ch = plane & 1;
    const int oh0 = blockIdx.y * TH;
    const int ow0 = blockIdx.x * TW;
    const float* xp = x + (size_t)plane * IMG * IMG;
    const float* yp = y + (size_t)plane * IMG * IMG;

    u64 wv2[6];
    #pragma unroll
    for (int k = 0; k < 6; k++) { float w = __ldg(&g_wv[ch][k]); wv2[k] = pack2(w, w); }

    // block-uniform interior test (tile + halo fully inside image)
    const bool interior = (blockIdx.x >= 1) & (blockIdx.x <= 6) &
                          (blockIdx.y >= 1) & (blockIdx.y <= 14);

    // ---- stage 1: vertical conv straight from global ----
    if (interior) {
        for (int t = tid; t < NTASK; t += NTHREADS) {
            int rgi = t / COLS;
            int col = t - rgi * COLS;
            int rg = rgi * RG;
            int r0 = oh0 + rg - HALO;
            const float* xb = xp + (ptrdiff_t)r0 * IMG + (ow0 + col - HALO);
            const float* yb = yp + (ptrdiff_t)r0 * IMG + (ow0 + col - HALO);

            u64 a1[RG], aq[RG];
            #pragma unroll
            for (int i = 0; i < RG; i++) { a1[i] = 0ull; aq[i] = 0ull; }

            #pragma unroll
            for (int tt = 0; tt < NROWS; tt++)   // 18 rows, unpredicated
                vaccum(__ldg(xb + tt * IMG), __ldg(yb + tt * IMG), tt, wv2, a1, aq);

            #pragma unroll
            for (int i = 0; i < RG; i++) {
                *reinterpret_cast<u64*>(&s_v1[(rg + i) * S2 + col]) = a1[i];
                *reinterpret_cast<u64*>(&s_vq[(rg + i) * S2 + col]) = aq[i];
            }
        }
    } else {
        for (int t = tid; t < NTASK; t += NTHREADS) {
            int rgi = t / COLS;
            int col = t - rgi * COLS;
            int rg = rgi * RG;
            int gc = ow0 + col - HALO;
            bool colok = (unsigned)gc < (unsigned)IMG;
            int r0 = oh0 + rg - HALO;
            const float* xb = xp + (ptrdiff_t)r0 * IMG + gc;
            const float* yb = yp + (ptrdiff_t)r0 * IMG + gc;

            u64 a1[RG], aq[RG];
            #pragma unroll
            for (int i = 0; i < RG; i++) { a1[i] = 0ull; aq[i] = 0ull; }

            #pragma unroll
            for (int tt = 0; tt < NROWS; tt++) {
                int gr = r0 + tt;
                float vx = 0.f, vy = 0.f;
                if (colok && (unsigned)gr < (unsigned)IMG) {
                    vx = __ldg(xb + tt * IMG);
                    vy = __ldg(yb + tt * IMG);
                }
                vaccum(vx, vy, tt, wv2, a1, aq);
            }
            #pragma unroll
            for (int i = 0; i < RG; i++) {
                *reinterpret_cast<u64*>(&s_v1[(rg + i) * S2 + col]) = a1[i];
                *reinterpret_cast<u64*>(&s_vq[(rg + i) * S2 + col]) = aq[i];
            }
        }
    }

    __syncthreads();

    // ---- stage 2: horizontal conv, single 8-px pass per thread ----
    u64 wh2[6];
    #pragma unroll
    for (int k = 0; k < 6; k++) { float w = __ldg(&g_wh[ch][k]); wh2[k] = pack2(w, w); }

    const int row = tid & 31;      // lanes span rows -> odd stride, conflict-free
    const int c0 = (tid >> 5) * 8;
    const float C1 = 1e-4f, C2 = 9e-4f;
    float lsum = 0.f;

    u64 h1[8], hq[8];
    #pragma unroll
    for (int p = 0; p < 8; p++) { h1[p] = 0ull; hq[p] = 0ull; }

    #pragma unroll
    for (int j = 0; j < 8 + KS - 1; j++) {      // 18 input cols (shared across all 8 px)
        u64 b1 = *reinterpret_cast<const u64*>(&s_v1[row * S2 + c0 + j]);
        u64 bq = *reinterpret_cast<const u64*>(&s_vq[row * S2 + c0 + j]);
        #pragma unroll
        for (int p = 0; p < 8; p++) {
            int k = j - p;
            if (k >= 0 && k < KS) {
                int wi = WIDX(k);
                h1[p] = fma2(wh2[wi], b1, h1[p]);
                hq[p] = fma2(wh2[wi], bq, hq[p]);
            }
        }
    }

    // ---- epilogue: SSIM per pixel ----
    #pragma unroll
    for (int p = 0; p < 8; p++) {
        float mux, muy; unpack2(h1[p], mux, muy);
        float es, exy;  unpack2(hq[p], es, exy);     // es = E[x^2+y^2]
        float muxy = mux * muy;
        float sxy  = fmaf(-mux, muy, exy);           // E[xy] - mux*muy
        float na   = fmaf(muxy, 2.0f, C1);
        float nb   = fmaf(sxy,  2.0f, C2);
        float m2   = fmaf(mux, mux, muy * muy);      // mux^2 + muy^2
        float dena = m2 + C1;
        float denb = (es - m2) + C2;                 // (sx + sy) + C2
        lsum += __fdividef(na * nb, dena * denb);
    }

    // ---- reduction: warp -> block -> one double atomic ----
    #pragma unroll
    for (int o = 16; o > 0; o >>= 1) lsum += __shfl_xor_sync(0xffffffffu, lsum, o);
    __shared__ float wsum[NTHREADS / 32];
    if ((tid & 31) == 0) wsum[tid >> 5] = lsum;
    __syncthreads();
    if (tid == 0) {
        float b = 0.f;
        #pragma unroll
        for (int w = 0; w < NTHREADS / 32; w++) b += wsum[w];
        atomicAdd(&g_accum, (double)b);
    }
}

__global__ void finalize_kernel(float* __restrict__ out) {
    // waits for all ssim_main blocks (implicit trigger at main's completion)
    cudaGridDependencySynchronize();
    if (threadIdx.x == 0) {
        out[0] = 1.0f - (float)(g_accum * (1.0 / (32.0 * 2.0 * 512.0 * 512.0)));
    }
}

extern "C" void kernel_launch(void* const* d_in, const int* in_sizes, int n_in,
                              void* d_out, int out_size) {
    const float* x = (const float*)d_in[0];
    const float* y = (const float*)d_in[1];
    const float* kern = (const float*)d_in[2];
    float* out = (float*)d_out;

    prep_kernel<<<1, 64>>>(kern);

    // ssim_main with programmatic dependent launch (overlaps prep tail)
    {
        cudaLaunchConfig_t cfg = {};
        cfg.gridDim = dim3(IMG / TW, IMG / TH, 64);
        cfg.blockDim = dim3(NTHREADS, 1, 1);
        cfg.dynamicSmemBytes = SMEM_BYTES;
        cfg.stream = 0;
        cudaLaunchAttribute attr[1];
        attr[0].id = cudaLaunchAttributeProgrammaticStreamSerialization;
        attr[0].val.programmaticStreamSerializationAllowed = 1;
        cfg.attrs = attr;
        cfg.numAttrs = 1;
        cudaLaunchKernelEx(&cfg, ssim_main, x, y);
    }

    // finalize with PDL (launch latency hides under main's tail wave)
    {
        cudaLaunchConfig_t cfg = {};
        cfg.gridDim = dim3(1, 1, 1);
        cfg.blockDim = dim3(32, 1, 1);
        cfg.dynamicSmemBytes = 0;
        cfg.stream = 0;
        cudaLaunchAttribute attr[1];
        attr[0].id = cudaLaunchAttributeProgrammaticStreamSerialization;
        attr[0].val.programmaticStreamSerializationAllowed = 1;
        cfg.attrs = attr;
        cfg.numAttrs = 1;
        cudaLaunchKernelEx(&cfg, finalize_kernel, out);
    }
}

// round 13
// speedup vs baseline: 1.1436x; 1.0035x over previous
#include <cuda_runtime.h>

#define IMG 512
#define TW 128
#define TH 16
#define KS 11
#define HALO 5
#define COLS (TW + 2*HALO)   /* 138 */
#define S2 139               /* float2 row stride (odd -> conflict-free) */
#define NTHREADS 256
/* smem: s_v1 16*139*8 + s_vq 16*139*8 = 35584 B -> 4 CTAs/SM */
#define SMEM_BYTES (TH*S2*8*2)

typedef unsigned long long u64;

__device__ double g_accum;
__device__ float g_wv[2][KS];
__device__ float g_wh[2][KS];

__device__ __forceinline__ u64 pack2(float x, float y) {
    u64 r; asm("mov.b64 %0, {%1,%2};" : "=l"(r) : "f"(x), "f"(y)); return r;
}
__device__ __forceinline__ void unpack2(u64 v, float& x, float& y) {
    asm("mov.b64 {%0,%1}, %2;" : "=f"(x), "=f"(y) : "l"(v));
}
__device__ __forceinline__ u64 fma2(u64 a, u64 b, u64 c) {
    u64 d; asm("fma.rn.f32x2 %0, %1, %2, %3;" : "=l"(d) : "l"(a), "l"(b), "l"(c)); return d;
}

/* Gaussian symmetry w[k] == w[10-k] (bit-exact: k2 = g outer g) */
#define WIDX(k) ((k) < 6 ? (k) : 10 - (k))

// Rank-1 factor reconstruction; resets accumulator each replay.
__global__ void prep_kernel(const float* __restrict__ kern) {
    int tid = threadIdx.x;
    if (tid == 0) g_accum = 0.0;
    if (tid < 64) {
        int ch = tid >> 5, lane = tid & 31;
        const float* kc = kern + ch * KS * KS;
        float s = 0.f;
        if (lane < KS) {
            #pragma unroll
            for (int j = 0; j < KS; j++) s += kc[lane * KS + j];       // row sums
        } else if (lane < 2 * KS) {
            #pragma unroll
            for (int j = 0; j < KS; j++) s += kc[j * KS + lane - KS];  // col sums
        }
        float contrib = (lane < KS) ? s : 0.f;
        #pragma unroll
        for (int o = 16; o > 0; o >>= 1) contrib += __shfl_xor_sync(0xffffffffu, contrib, o);
        if (lane < KS)           g_wv[ch][lane] = s;
        else if (lane < 2 * KS)  g_wh[ch][lane - KS] = s / contrib;
    }
}

extern __shared__ float2 smem_dyn[];

/* accumulate one input px into R row accumulators (streams (x,y),(x^2+y^2,xy)) */
template<int R>
__device__ __forceinline__ void vacc(float vx, float vy, int tt,
                                     const u64* __restrict__ wv2,
                                     u64* a1, u64* aq) {
    u64 u = pack2(vx, vy);
    float s2  = fmaf(vy, vy, vx * vx);
    float pxy = vx * vy;
    u64 q = pack2(s2, pxy);
    #pragma unroll
    for (int i = 0; i < R; i++) {
        int k = tt - i;
        if (k >= 0 && k < KS) {
            int wi = WIDX(k);
            a1[i] = fma2(wv2[wi], u, a1[i]);
            aq[i] = fma2(wv2[wi], q, aq[i]);
        }
    }
}

/* one vertical-conv task: column m (tile-local), output rows [rg, rg+R) */
template<int R>
__device__ __forceinline__ void run_task(int m, int rg, int oh0, int ow0,
                                         const float* __restrict__ xp,
                                         const float* __restrict__ yp,
                                         const u64* __restrict__ wv2,
                                         float2* s_v1, float2* s_vq) {
    const int NR = R + KS - 1;
    int gc = ow0 + m - HALO;
    bool colok = (unsigned)gc < (unsigned)IMG;
    int r0 = oh0 + rg - HALO;
    bool rowok = (r0 >= 0) && (r0 + NR <= IMG);
    const float* xb = xp + (ptrdiff_t)r0 * IMG + gc;
    const float* yb = yp + (ptrdiff_t)r0 * IMG + gc;

    u64 a1[R], aq[R];
    #pragma unroll
    for (int i = 0; i < R; i++) { a1[i] = 0ull; aq[i] = 0ull; }

    if (colok && rowok) {
        #pragma unroll
        for (int tt = 0; tt < NR; tt++)            // unpredicated fast path
            vacc<R>(__ldg(xb + tt * IMG), __ldg(yb + tt * IMG), tt, wv2, a1, aq);
    } else {
        #pragma unroll
        for (int tt = 0; tt < NR; tt++) {
            int gr = r0 + tt;
            float vx = 0.f, vy = 0.f;
            if (colok && (unsigned)gr < (unsigned)IMG) {
                vx = __ldg(xb + tt * IMG);
                vy = __ldg(yb + tt * IMG);
            }
            vacc<R>(vx, vy, tt, wv2, a1, aq);
        }
    }
    #pragma unroll
    for (int i = 0; i < R; i++) {
        *reinterpret_cast<u64*>(&s_v1[(rg + i) * S2 + m]) = a1[i];
        *reinterpret_cast<u64*>(&s_vq[(rg + i) * S2 + m]) = aq[i];
    }
}

__global__ __launch_bounds__(NTHREADS, 4)
void ssim_main(const float* __restrict__ x, const float* __restrict__ y) {
    float2* s_v1 = smem_dyn;                  // [TH][S2] (sum_x, sum_y)
    float2* s_vq = s_v1 + TH * S2;            // [TH][S2] (sum_{x^2+y^2}, sum_xy)

    const int tid = threadIdx.x;
    const int plane = blockIdx.z;             // 64 = 32 batch * 2 chan (NCHW)
    const int ch = plane & 1;
    const int oh0 = blockIdx.y * TH;
    const int ow0 = blockIdx.x * TW;
    const float* xp = x + (size_t)plane * IMG * IMG;
    const float* yp = y + (size_t)plane * IMG * IMG;

    u64 wv2[6];
    #pragma unroll
    for (int k = 0; k < 6; k++) { float w = __ldg(&g_wv[ch][k]); wv2[k] = pack2(w, w); }

    // ---- stage 1: 276 tasks = 256 RG8 (1:1 threads) + 20 split as 40 RG4 ----
    {
        int m   = (tid < COLS) ? tid : tid - COLS;   // cols 0..137 / 0..117
        int rgi = (tid < COLS) ? 0 : 1;
        run_task<8>(m, rgi * 8, oh0, ow0, xp, yp, wv2, s_v1, s_vq);

        if (tid < 40) {                               // leftover cols 118..137, rgi=1
            int m2  = (COLS - 20) + (tid >> 1);
            int rg2 = 8 + (tid & 1) * 4;
            run_task<4>(m2, rg2, oh0, ow0, xp, yp, wv2, s_v1, s_vq);
        }
    }

    __syncthreads();

    // ---- stage 2: horizontal conv, 8 px per thread ----
    u64 wh2[6];
    #pragma unroll
    for (int k = 0; k < 6; k++) { float w = __ldg(&g_wh[ch][k]); wh2[k] = pack2(w, w); }

    const int row = tid & 15;                 // 16 rows; half-warp phases conflict-free
    const int c0 = (tid >> 4) * 8;            // 16 col groups * 8 = 128
    const float C1 = 1e-4f, C2 = 9e-4f;
    float lsum = 0.f;

    u64 h1[8], hq[8];
    #pragma unroll
    for (int p = 0; p < 8; p++) { h1[p] = 0ull; hq[p] = 0ull; }

    #pragma unroll
    for (int j = 0; j < 8 + KS - 1; j++) {    // 18 input cols shared across 8 px
        u64 b1 = *reinterpret_cast<const u64*>(&s_v1[row * S2 + c0 + j]);
        u64 bq = *reinterpret_cast<const u64*>(&s_vq[row * S2 + c0 + j]);
        #pragma unroll
        for (int p = 0; p < 8; p++) {
            int k = j - p;
            if (k >= 0 && k < KS) {
                int wi = WIDX(k);
                h1[p] = fma2(wh2[wi], b1, h1[p]);
                hq[p] = fma2(wh2[wi], bq, hq[p]);
            }
        }
    }

    // ---- epilogue: SSIM per pixel ----
    #pragma unroll
    for (int p = 0; p < 8; p++) {
        float mux, muy; unpack2(h1[p], mux, muy);
        float es, exy;  unpack2(hq[p], es, exy);     // es = E[x^2+y^2]
        float muxy = mux * muy;
        float sxy  = fmaf(-mux, muy, exy);
        float na   = fmaf(muxy, 2.0f, C1);
        float nb   = fmaf(sxy,  2.0f, C2);
        float m2   = fmaf(mux, mux, muy * muy);
        float dena = m2 + C1;
        float denb = (es - m2) + C2;
        lsum += __fdividef(na * nb, dena * denb);
    }

    // ---- reduction: warp -> block -> one double atomic ----
    #pragma unroll
    for (int o = 16; o > 0; o >>= 1) lsum += __shfl_xor_sync(0xffffffffu, lsum, o);
    __shared__ float wsum[NTHREADS / 32];
    if ((tid & 31) == 0) wsum[tid >> 5] = lsum;
    __syncthreads();
    if (tid == 0) {
        float b = 0.f;
        #pragma unroll
        for (int w = 0; w < NTHREADS / 32; w++) b += wsum[w];
        atomicAdd(&g_accum, (double)b);
    }
}

__global__ void finalize_kernel(float* __restrict__ out) {
    if (threadIdx.x == 0) {
        out[0] = 1.0f - (float)(g_accum * (1.0 / (32.0 * 2.0 * 512.0 * 512.0)));
    }
}

extern "C" void kernel_launch(void* const* d_in, const int* in_sizes, int n_in,
                              void* d_out, int out_size) {
    const float* x = (const float*)d_in[0];
    const float* y = (const float*)d_in[1];
    const float* kern = (const float*)d_in[2];
    float* out = (float*)d_out;

    prep_kernel<<<1, 64>>>(kern);
    dim3 grid(IMG / TW, IMG / TH, 64);
    ssim_main<<<grid, NTHREADS, SMEM_BYTES>>>(x, y);
    finalize_kernel<<<1, 32>>>(out);
}